// round 4
// baseline (speedup 1.0000x reference)
#include <cuda_runtime.h>
#include <cstdint>

// Problem constants
constexpr int Bc = 8, Lc = 4096;
constexpr int Mrows = Bc * Lc;          // 32768
constexpr int NCHUNK = 64, CLEN = 64;   // 64 chunks of 64 steps

// Scratch (static device arrays -- no allocation allowed)
__device__ float g_f [(size_t)Mrows * 512];   // f = dt_s*Bu : [bl][2p+c] (re/im interleaved)
__device__ float g_ys[(size_t)Mrows * 512];   // ys, same interleaved layout
// Fragment-layout operand matrices: [k8][j(n8)][lane(32)][slot(2)]
__device__ float g_BopP[256 * 512];           // K=256 (h), N=512 (2p+c): 32 k8 x 64 j
__device__ float g_CopP[512 * 256];           // K=512 (2p+c), N=256 (h): 64 k8 x 32 j
__device__ float g_m11[256], g_m12[256], g_dts[256];
__device__ float g_cf  [Bc * 256 * NCHUNK * 4]; // [b][p][ch] float4 (x1r,x1i,x2r,x2i)
__device__ float g_init[Bc * 256 * NCHUNK * 4]; // same layout

__device__ __forceinline__ float tf32_rna(float x) {
    uint32_t u;
    asm("cvt.rna.tf32.f32 %0, %1;" : "=r"(u) : "f"(x));
    return __uint_as_float(u);
}

__device__ __forceinline__ void cp_async16(void* smem, const void* gmem) {
    uint32_t s = (uint32_t)__cvta_generic_to_shared(smem);
    asm volatile("cp.async.ca.shared.global [%0], [%1], 16;\n" :: "r"(s), "l"(gmem));
}

__device__ __forceinline__ void mma_tf32_v(float c[4], const uint32_t a[4], const uint32_t b[2]) {
    asm volatile(
        "mma.sync.aligned.m16n8k8.row.col.f32.tf32.tf32.f32 "
        "{%0,%1,%2,%3}, {%4,%5,%6,%7}, {%8,%9}, {%0,%1,%2,%3};\n"
        : "+f"(c[0]), "+f"(c[1]), "+f"(c[2]), "+f"(c[3])
        : "r"(a[0]), "r"(a[1]), "r"(a[2]), "r"(a[3]), "r"(b[0]), "r"(b[1]));
}

// ---------------------------------------------------------------------------
// Prep: per-p recurrence params + operand matrices in MMA fragment layout.
// Fragment layout for B operand of m16n8k8 (k x n, col-major n8 tiles):
//   elem (k, n): k8=k>>3, j=n>>3, t=k&3, hk=(k>>2)&1, g=n&7
//   offset = ((k8*NJ + j)*32 + g*4 + t)*2 + hk
// ---------------------------------------------------------------------------
__global__ void prep_kernel(const float* __restrict__ Ad, const float* __restrict__ Gd,
                            const float* __restrict__ dt, const float* __restrict__ Bm,
                            const float* __restrict__ Cm) {
    int h = blockIdx.x;          // 0..255
    int n = threadIdx.x;         // 0..511
    int p = n >> 1;
    int c = n & 1;
    float dts = 1.0f / (1.0f + expf(-dt[p]));
    float G = fmaxf(Gd[p], dts * Ad[p]);
    float A = fmaxf(Ad[p], 0.25f * G * G);

    // Bop[h][n] = dt_s[p]*B[p][h][c], fragment layout with k=h (NJ=64)
    {
        int k8 = h >> 3, j = n >> 3, t = h & 3, hk = (h >> 2) & 1, g = n & 7;
        g_BopP[((k8 * 64 + j) * 32 + g * 4 + t) * 2 + hk] =
            tf32_rna(dts * Bm[p * 512 + h * 2 + c]);
    }
    // Cop[n][h] = +Cre[h][p] / -Cim[h][p], fragment layout with k=n (NJ=32)
    {
        float cv = Cm[h * 512 + p * 2 + c];
        int k8 = n >> 3, j = h >> 3, t = n & 3, hk = (n >> 2) & 1, g = h & 7;
        g_CopP[((k8 * 32 + j) * 32 + g * 4 + t) * 2 + hk] =
            tf32_rna(c ? -cv : cv);
    }

    if (h == 0 && c == 0) {
        g_m11[p] = 1.0f - dts * G;
        g_m12[p] = -dts * A;
        g_dts[p] = dts;          // m21; m22 == 1
    }
}

// ---------------------------------------------------------------------------
// tf32 GEMM, fragment-layout smem. C[M x N] = A[M x K] @ B[K x N] (+ epilogue)
// 128x128x32 tile, 8 warps (2x4), warp tile 64x32.
// A smem: [m16(8)][k8(4)][lane(32)][slot(4)]  -> LDS.128 per fragment
// B smem: [k8(4)][j(16)][lane(32)][slot(2)]   -> LDS.64  per fragment
// ---------------------------------------------------------------------------
template <int N, int K, bool EPI>
__global__ void __launch_bounds__(256)
gemm_tf32(const float* __restrict__ A, const float* __restrict__ BmP,
          float* __restrict__ C, const float* __restrict__ U,
          const float* __restrict__ Dv) {
    extern __shared__ float sm[];
    float* As = sm;                // 2 stages * 4096 floats (16KB)
    float* Bs = sm + 2 * 4096;     // 2 stages * 4096 floats (16KB)

    const int tid  = threadIdx.x;
    const int lane = tid & 31, warp = tid >> 5;
    const int g = lane >> 2, t = lane & 3;
    const int wr = (warp & 1) * 64, wc = (warp >> 1) * 32;
    const int m0 = blockIdx.y * 128, n0 = blockIdx.x * 128;
    const int nk = K / 32;
    const int NJ = N / 8;
    const int j0 = n0 >> 3;

    float acc[4][4][4];
#pragma unroll
    for (int i = 0; i < 4; i++)
#pragma unroll
        for (int j = 0; j < 4; j++)
#pragma unroll
            for (int q = 0; q < 4; q++) acc[i][j][q] = 0.0f;

    float4 aReg[4];

    auto ldgA = [&](int kt) {
#pragma unroll
        for (int i = 0; i < 4; i++) {
            int idx = i * 256 + tid;
            int m = idx >> 3, c4 = idx & 7;
            aReg[i] = *reinterpret_cast<const float4*>(
                A + (size_t)(m0 + m) * K + kt * 32 + c4 * 4);
        }
    };
    // scatter-store into fragment layout (with tf32 rounding)
    auto stsA = [&](int s) {
#pragma unroll
        for (int i = 0; i < 4; i++) {
            int idx = i * 256 + tid;
            int m = idx >> 3, c4 = idx & 7;
            int m16 = m >> 4, gg = m & 7, hr = (m >> 3) & 1;
            int k8 = c4 >> 1, hc = c4 & 1;
            float* p0 = As + s * 4096 + (m16 * 4 + k8) * 128 + gg * 16 + hr + 2 * hc;
            float4 v = aReg[i];
            p0[0]  = tf32_rna(v.x);
            p0[4]  = tf32_rna(v.y);
            p0[8]  = tf32_rna(v.z);
            p0[12] = tf32_rna(v.w);
        }
    };
    auto ldB = [&](int s, int kt) {
#pragma unroll
        for (int kk = 0; kk < 4; kk++) {
            cp_async16(Bs + s * 4096 + kk * 1024 + tid * 4,
                       BmP + (size_t)((kt * 4 + kk) * NJ + j0) * 64 + tid * 4);
        }
        asm volatile("cp.async.commit_group;\n" ::);
    };

    // prologue
    ldB(0, 0);
    ldgA(0); stsA(0);
    asm volatile("cp.async.wait_group 0;\n" ::);
    __syncthreads();

    for (int kt = 0; kt < nk; kt++) {
        int s = kt & 1;
        bool more = (kt + 1 < nk);
        if (more) { ldB(s ^ 1, kt + 1); ldgA(kt + 1); }

        const float* Asb = As + s * 4096;
        const float* Bsb = Bs + s * 4096;
#pragma unroll
        for (int kk = 0; kk < 4; kk++) {
            uint32_t af[4][4];
#pragma unroll
            for (int mt = 0; mt < 4; mt++) {
                const float4 v = *reinterpret_cast<const float4*>(
                    Asb + (((wr >> 4) + mt) * 4 + kk) * 128 + lane * 4);
                af[mt][0] = __float_as_uint(v.x);
                af[mt][1] = __float_as_uint(v.y);
                af[mt][2] = __float_as_uint(v.z);
                af[mt][3] = __float_as_uint(v.w);
            }
            uint32_t bf[4][2];
#pragma unroll
            for (int nt = 0; nt < 4; nt++) {
                const float2 v = *reinterpret_cast<const float2*>(
                    Bsb + (kk * 16 + (wc >> 3) + nt) * 64 + lane * 2);
                bf[nt][0] = __float_as_uint(v.x);
                bf[nt][1] = __float_as_uint(v.y);
            }
#pragma unroll
            for (int mt = 0; mt < 4; mt++)
#pragma unroll
                for (int nt = 0; nt < 4; nt++)
                    mma_tf32_v(acc[mt][nt], af[mt], bf[nt]);
        }
        if (more) {
            stsA(s ^ 1);
            asm volatile("cp.async.wait_group 0;\n" ::);
        }
        __syncthreads();
    }

    // epilogue
#pragma unroll
    for (int mt = 0; mt < 4; mt++) {
#pragma unroll
        for (int nt = 0; nt < 4; nt++) {
            int r0 = m0 + wr + mt * 16 + g;
            int cc = n0 + wc + nt * 8 + 2 * t;
            float v0 = acc[mt][nt][0], v1 = acc[mt][nt][1];
            float v2 = acc[mt][nt][2], v3 = acc[mt][nt][3];
            if (EPI) {
                float d0 = Dv[cc], d1 = Dv[cc + 1];
                v0 += d0 * U[(size_t)r0 * 256 + cc];
                v1 += d1 * U[(size_t)r0 * 256 + cc + 1];
                v2 += d0 * U[(size_t)(r0 + 8) * 256 + cc];
                v3 += d1 * U[(size_t)(r0 + 8) * 256 + cc + 1];
            }
            *reinterpret_cast<float2*>(C + (size_t)r0 * N + cc) = make_float2(v0, v1);
            *reinterpret_cast<float2*>(C + (size_t)(r0 + 8) * N + cc) = make_float2(v2, v3);
        }
    }
}

// ---------------------------------------------------------------------------
// Scan phase 1: per-chunk local scan (zero init) -> chunk-final states
// ---------------------------------------------------------------------------
__global__ void scan_local() {
    int b = blockIdx.x >> 6;
    int ch = blockIdx.x & 63;
    int p = threadIdx.x;
    float m11 = g_m11[p], m12 = g_m12[p], m21 = g_dts[p];
    float x1r = 0, x1i = 0, x2r = 0, x2i = 0;
    const float2* f = reinterpret_cast<const float2*>(g_f)
                      + ((size_t)(b * Lc + ch * CLEN)) * 256 + p;
#pragma unroll 8
    for (int j = 0; j < CLEN; j++) {
        float2 fv = f[(size_t)j * 256];
        float n1r = fmaf(m11, x1r, fmaf(m12, x2r, fv.x));
        float n2r = fmaf(m21, x1r, x2r);
        float n1i = fmaf(m11, x1i, fmaf(m12, x2i, fv.y));
        float n2i = fmaf(m21, x1i, x2i);
        x1r = n1r; x2r = n2r; x1i = n1i; x2i = n2i;
    }
    reinterpret_cast<float4*>(g_cf)[(b * 256 + p) * 64 + ch] =
        make_float4(x1r, x1i, x2r, x2i);
}

// ---------------------------------------------------------------------------
// Scan phase 2: warp-parallel cross-chunk combine (Kogge-Stone over 32 lanes)
// ---------------------------------------------------------------------------
__global__ void __launch_bounds__(256) scan_combine() {
    const unsigned FULL = 0xFFFFFFFFu;
    int wg = blockIdx.x * 8 + (threadIdx.x >> 5);   // 0..2047
    int lane = threadIdx.x & 31;
    int b = wg >> 8, p = wg & 255;

    float m11 = g_m11[p], m12 = g_m12[p], m21 = g_dts[p];
    // P = M^64 via 6 squarings; M = [m11 m12; m21 1]
    float pa = m11, pb = m12, pc = m21, pd = 1.0f;
#pragma unroll
    for (int i = 0; i < 6; i++) {
        float na = fmaf(pa, pa, pb * pc);
        float nb = fmaf(pa, pb, pb * pd);
        float nc = fmaf(pc, pa, pd * pc);
        float nd = fmaf(pc, pb, pd * pd);
        pa = na; pb = nb; pc = nc; pd = nd;
    }

    const float4* cf = reinterpret_cast<const float4*>(g_cf) + (size_t)(b * 256 + p) * 64;
    float4 v0 = cf[2 * lane];
    float4 v1 = cf[2 * lane + 1];

    float w1r = fmaf(pa, v0.x, fmaf(pb, v0.z, v1.x));
    float w1i = fmaf(pa, v0.y, fmaf(pb, v0.w, v1.y));
    float w2r = fmaf(pc, v0.x, fmaf(pd, v0.z, v1.z));
    float w2i = fmaf(pc, v0.y, fmaf(pd, v0.w, v1.w));
    float ma = fmaf(pa, pa, pb * pc), mb = fmaf(pa, pb, pb * pd);
    float mc = fmaf(pc, pa, pd * pc), md = fmaf(pc, pb, pd * pd);

#pragma unroll
    for (int d = 1; d < 32; d <<= 1) {
        float oa = __shfl_up_sync(FULL, ma, d);
        float ob = __shfl_up_sync(FULL, mb, d);
        float oc = __shfl_up_sync(FULL, mc, d);
        float od = __shfl_up_sync(FULL, md, d);
        float o1r = __shfl_up_sync(FULL, w1r, d);
        float o1i = __shfl_up_sync(FULL, w1i, d);
        float o2r = __shfl_up_sync(FULL, w2r, d);
        float o2i = __shfl_up_sync(FULL, w2i, d);
        if (lane >= d) {
            w1r = fmaf(ma, o1r, fmaf(mb, o2r, w1r));
            w1i = fmaf(ma, o1i, fmaf(mb, o2i, w1i));
            w2r = fmaf(mc, o1r, fmaf(md, o2r, w2r));
            w2i = fmaf(mc, o1i, fmaf(md, o2i, w2i));
            float na = fmaf(ma, oa, mb * oc), nb = fmaf(ma, ob, mb * od);
            float nc = fmaf(mc, oa, md * oc), nd = fmaf(mc, ob, md * od);
            ma = na; mb = nb; mc = nc; md = nd;
        }
    }

    float e1r = __shfl_up_sync(FULL, w1r, 1);
    float e1i = __shfl_up_sync(FULL, w1i, 1);
    float e2r = __shfl_up_sync(FULL, w2r, 1);
    float e2i = __shfl_up_sync(FULL, w2i, 1);
    if (lane == 0) { e1r = e1i = e2r = e2i = 0.0f; }

    float4* gi = reinterpret_cast<float4*>(g_init) + (size_t)(b * 256 + p) * 64;
    gi[2 * lane] = make_float4(e1r, e1i, e2r, e2i);
    gi[2 * lane + 1] = make_float4(
        fmaf(pa, e1r, fmaf(pb, e2r, v0.x)),
        fmaf(pa, e1i, fmaf(pb, e2i, v0.y)),
        fmaf(pc, e1r, fmaf(pd, e2r, v0.z)),
        fmaf(pc, e1i, fmaf(pd, e2i, v0.w)));
}

// ---------------------------------------------------------------------------
// Scan phase 3: re-scan each chunk from corrected init, write ys (x2, interleaved)
// ---------------------------------------------------------------------------
__global__ void scan_final() {
    int b = blockIdx.x >> 6;
    int ch = blockIdx.x & 63;
    int p = threadIdx.x;
    float m11 = g_m11[p], m12 = g_m12[p], m21 = g_dts[p];
    float4 iv = reinterpret_cast<const float4*>(g_init)[(b * 256 + p) * 64 + ch];
    float x1r = iv.x, x1i = iv.y, x2r = iv.z, x2i = iv.w;
    const float2* f = reinterpret_cast<const float2*>(g_f)
                      + ((size_t)(b * Lc + ch * CLEN)) * 256 + p;
    float2* ys = reinterpret_cast<float2*>(g_ys)
                 + ((size_t)(b * Lc + ch * CLEN)) * 256 + p;
#pragma unroll 8
    for (int j = 0; j < CLEN; j++) {
        float2 fv = f[(size_t)j * 256];
        float n1r = fmaf(m11, x1r, fmaf(m12, x2r, fv.x));
        float n2r = fmaf(m21, x1r, x2r);
        float n1i = fmaf(m11, x1i, fmaf(m12, x2i, fv.y));
        float n2i = fmaf(m21, x1i, x2i);
        x1r = n1r; x2r = n2r; x1i = n1i; x2i = n2i;
        ys[(size_t)j * 256] = make_float2(x2r, x2i);
    }
}

// ---------------------------------------------------------------------------
extern "C" void kernel_launch(void* const* d_in, const int* in_sizes, int n_in,
                              void* d_out, int out_size) {
    const float* u  = (const float*)d_in[0];
    const float* Ad = (const float*)d_in[1];
    const float* Gd = (const float*)d_in[2];
    const float* dt = (const float*)d_in[3];
    const float* Bm = (const float*)d_in[4];
    const float* Cm = (const float*)d_in[5];
    const float* Dv = (const float*)d_in[6];
    float* out = (float*)d_out;

    float *fptr, *ysptr, *bop, *cop;
    cudaGetSymbolAddress((void**)&fptr,  g_f);
    cudaGetSymbolAddress((void**)&ysptr, g_ys);
    cudaGetSymbolAddress((void**)&bop,   g_BopP);
    cudaGetSymbolAddress((void**)&cop,   g_CopP);

    const int smem_bytes = 4 * 4096 * 4;  // 64 KB
    cudaFuncSetAttribute(gemm_tf32<512, 256, false>,
                         cudaFuncAttributeMaxDynamicSharedMemorySize, smem_bytes);
    cudaFuncSetAttribute(gemm_tf32<256, 512, true>,
                         cudaFuncAttributeMaxDynamicSharedMemorySize, smem_bytes);

    prep_kernel<<<256, 512>>>(Ad, Gd, dt, Bm, Cm);

    // GEMM1: f[bl][n(512)] = u[bl][h] @ Bop[h][n]
    gemm_tf32<512, 256, false><<<dim3(4, 256), 256, smem_bytes>>>(u, bop, fptr, nullptr, nullptr);

    scan_local  <<<Bc * NCHUNK, 256>>>();
    scan_combine<<<256, 256>>>();
    scan_final  <<<Bc * NCHUNK, 256>>>();

    // GEMM2: out[bl][h] = ys[bl][kk(512)] @ Cop[kk][h] + D[h]*u[bl][h]
    gemm_tf32<256, 512, true><<<dim3(2, 256), 256, smem_bytes>>>(ysptr, cop, out, u, Dv);
}

// round 5
// speedup vs baseline: 1.0765x; 1.0765x over previous
#include <cuda_runtime.h>
#include <cstdint>

// Problem constants
constexpr int Bc = 8, Lc = 4096;
constexpr int Mrows = Bc * Lc;          // 32768
constexpr int NCHUNK = 64, CLEN = 64;   // 64 chunks of 64 steps

// Scratch (static device arrays -- no allocation allowed)
__device__ float g_f [(size_t)Mrows * 512];   // f = dt_s*Bu : [bl][2p+c] (re/im interleaved)
__device__ float g_Bop[256 * 512];            // [h][n], n = 2p+c, dt_s folded
__device__ float g_Cop[512 * 256];            // [kk][h], kk = 2p+c: +Cre / -Cim
__device__ float g_m11[256], g_m12[256], g_dts[256];
__device__ float g_cf  [Bc * 256 * NCHUNK * 4]; // [b][p][ch] float4 (x1r,x1i,x2r,x2i)
__device__ float g_init[Bc * 256 * NCHUNK * 4]; // same layout

__device__ __forceinline__ float tf32_rna(float x) {
    uint32_t u;
    asm("cvt.rna.tf32.f32 %0, %1;" : "=r"(u) : "f"(x));
    return __uint_as_float(u);
}

__device__ __forceinline__ void cp_async16(void* smem, const void* gmem) {
    uint32_t s = (uint32_t)__cvta_generic_to_shared(smem);
    asm volatile("cp.async.ca.shared.global [%0], [%1], 16;\n" :: "r"(s), "l"(gmem));
}

__device__ __forceinline__ void mma_tf32_v(float c[4], const uint32_t a[4], const uint32_t b[2]) {
    asm volatile(
        "mma.sync.aligned.m16n8k8.row.col.f32.tf32.tf32.f32 "
        "{%0,%1,%2,%3}, {%4,%5,%6,%7}, {%8,%9}, {%0,%1,%2,%3};\n"
        : "+f"(c[0]), "+f"(c[1]), "+f"(c[2]), "+f"(c[3])
        : "r"(a[0]), "r"(a[1]), "r"(a[2]), "r"(a[3]), "r"(b[0]), "r"(b[1]));
}

// ---------------------------------------------------------------------------
// Prep: per-p recurrence params + operand matrices (tf32-rounded, scaled)
// Layout: interleaved n = 2p + c  (c=0 re, c=1 im)
// ---------------------------------------------------------------------------
__global__ void prep_kernel(const float* __restrict__ Ad, const float* __restrict__ Gd,
                            const float* __restrict__ dt, const float* __restrict__ Bm,
                            const float* __restrict__ Cm) {
    int h = blockIdx.x;          // 0..255
    int n = threadIdx.x;         // 0..511
    int p = n >> 1;
    int c = n & 1;
    float dts = 1.0f / (1.0f + expf(-dt[p]));
    float G = fmaxf(Gd[p], dts * Ad[p]);
    float A = fmaxf(Ad[p], 0.25f * G * G);

    // Bop[h][2p+c] = dt_s[p] * B[p][h][c]
    g_Bop[h * 512 + n] = tf32_rna(dts * Bm[p * 512 + h * 2 + c]);
    // Cop[2p+c][h] = +Cre[h][p] (c==0) | -Cim[h][p] (c==1)
    float cv = Cm[h * 512 + p * 2 + c];
    g_Cop[n * 256 + h] = tf32_rna(c ? -cv : cv);

    if (h == 0 && c == 0) {
        g_m11[p] = 1.0f - dts * G;
        g_m12[p] = -dts * A;
        g_dts[p] = dts;          // m21; m22 == 1
    }
}

// ---------------------------------------------------------------------------
// tf32 GEMM (round-2 proven version): C[M x N] = A[M x K] @ B[K x N]
// 128x128x32 block tile, 8 warps (2x4), warp tile 64x32, m16n8k8 mma
// ---------------------------------------------------------------------------
template <int N, int K>
__global__ void __launch_bounds__(256, 2)
gemm_tf32(const float* __restrict__ A, const float* __restrict__ Bm,
          float* __restrict__ C) {
    extern __shared__ float sm[];
    float* As = sm;                // 2 stages * 128*36
    float* Bs = sm + 2 * 128 * 36; // 2 stages * 32*136

    const int tid  = threadIdx.x;
    const int lane = tid & 31, warp = tid >> 5;
    const int g = lane >> 2, t = lane & 3;
    const int wr = (warp & 1) * 64, wc = (warp >> 1) * 32;
    const int m0 = blockIdx.y * 128, n0 = blockIdx.x * 128;
    const int nk = K / 32;

    float acc[4][4][4];
#pragma unroll
    for (int i = 0; i < 4; i++)
#pragma unroll
        for (int j = 0; j < 4; j++)
#pragma unroll
            for (int q = 0; q < 4; q++) acc[i][j][q] = 0.0f;

    float4 aReg[4];

    auto ldgA = [&](int kt) {
#pragma unroll
        for (int i = 0; i < 4; i++) {
            int idx = i * 256 + tid;
            int m = idx >> 3, c4 = idx & 7;
            aReg[i] = *reinterpret_cast<const float4*>(
                A + (size_t)(m0 + m) * K + kt * 32 + c4 * 4);
        }
    };
    auto stsA = [&](int s) {
#pragma unroll
        for (int i = 0; i < 4; i++) {
            int idx = i * 256 + tid;
            int m = idx >> 3, c4 = idx & 7;
            float4 v = aReg[i];
            v.x = tf32_rna(v.x); v.y = tf32_rna(v.y);
            v.z = tf32_rna(v.z); v.w = tf32_rna(v.w);
            *reinterpret_cast<float4*>(As + s * 4608 + m * 36 + c4 * 4) = v;
        }
    };
    auto ldB = [&](int s, int kt) {
#pragma unroll
        for (int i = 0; i < 4; i++) {
            int idx = i * 256 + tid;
            int k = idx >> 5, c = idx & 31;
            cp_async16(Bs + s * 4352 + k * 136 + c * 4,
                       Bm + (size_t)(kt * 32 + k) * N + n0 + c * 4);
        }
        asm volatile("cp.async.commit_group;\n" ::);
    };

    // prologue
    ldB(0, 0);
    ldgA(0); stsA(0);
    asm volatile("cp.async.wait_group 0;\n" ::);
    __syncthreads();

    for (int kt = 0; kt < nk; kt++) {
        int s = kt & 1;
        bool more = (kt + 1 < nk);
        if (more) { ldB(s ^ 1, kt + 1); ldgA(kt + 1); }

        const float* Asb = As + s * 4608;
        const float* Bsb = Bs + s * 4352;
#pragma unroll
        for (int kk = 0; kk < 4; kk++) {
            uint32_t af[4][4];
#pragma unroll
            for (int mt = 0; mt < 4; mt++) {
                int row = wr + mt * 16 + g;
                int col = kk * 8 + t;
                af[mt][0] = __float_as_uint(Asb[row * 36 + col]);
                af[mt][1] = __float_as_uint(Asb[(row + 8) * 36 + col]);
                af[mt][2] = __float_as_uint(Asb[row * 36 + col + 4]);
                af[mt][3] = __float_as_uint(Asb[(row + 8) * 36 + col + 4]);
            }
            uint32_t bf[4][2];
#pragma unroll
            for (int nt = 0; nt < 4; nt++) {
                int col = wc + nt * 8 + g;
                bf[nt][0] = __float_as_uint(Bsb[(kk * 8 + t) * 136 + col]);
                bf[nt][1] = __float_as_uint(Bsb[(kk * 8 + t + 4) * 136 + col]);
            }
#pragma unroll
            for (int mt = 0; mt < 4; mt++)
#pragma unroll
                for (int nt = 0; nt < 4; nt++)
                    mma_tf32_v(acc[mt][nt], af[mt], bf[nt]);
        }
        if (more) {
            stsA(s ^ 1);
            asm volatile("cp.async.wait_group 0;\n" ::);
        }
        __syncthreads();
    }

    // epilogue
#pragma unroll
    for (int mt = 0; mt < 4; mt++) {
#pragma unroll
        for (int nt = 0; nt < 4; nt++) {
            int r0 = m0 + wr + mt * 16 + g;
            int cc = n0 + wc + nt * 8 + 2 * t;
            *reinterpret_cast<float2*>(C + (size_t)r0 * N + cc) =
                make_float2(acc[mt][nt][0], acc[mt][nt][1]);
            *reinterpret_cast<float2*>(C + (size_t)(r0 + 8) * N + cc) =
                make_float2(acc[mt][nt][2], acc[mt][nt][3]);
        }
    }
}

// ---------------------------------------------------------------------------
// Scan phase 1: per-chunk local scan (zero init) -> chunk-final states
// ---------------------------------------------------------------------------
__global__ void scan_local() {
    int b = blockIdx.x >> 6;
    int ch = blockIdx.x & 63;
    int p = threadIdx.x;
    float m11 = g_m11[p], m12 = g_m12[p], m21 = g_dts[p];
    float x1r = 0, x1i = 0, x2r = 0, x2i = 0;
    const float2* f = reinterpret_cast<const float2*>(g_f)
                      + ((size_t)(b * Lc + ch * CLEN)) * 256 + p;
#pragma unroll 8
    for (int j = 0; j < CLEN; j++) {
        float2 fv = f[(size_t)j * 256];
        float n1r = fmaf(m11, x1r, fmaf(m12, x2r, fv.x));
        float n2r = fmaf(m21, x1r, x2r);
        float n1i = fmaf(m11, x1i, fmaf(m12, x2i, fv.y));
        float n2i = fmaf(m21, x1i, x2i);
        x1r = n1r; x2r = n2r; x1i = n1i; x2i = n2i;
    }
    reinterpret_cast<float4*>(g_cf)[(b * 256 + p) * 64 + ch] =
        make_float4(x1r, x1i, x2r, x2i);
}

// ---------------------------------------------------------------------------
// Scan phase 2: warp-parallel cross-chunk combine (Kogge-Stone over 32 lanes)
// ---------------------------------------------------------------------------
__global__ void __launch_bounds__(256) scan_combine() {
    const unsigned FULL = 0xFFFFFFFFu;
    int wg = blockIdx.x * 8 + (threadIdx.x >> 5);   // 0..2047
    int lane = threadIdx.x & 31;
    int b = wg >> 8, p = wg & 255;

    float m11 = g_m11[p], m12 = g_m12[p], m21 = g_dts[p];
    // P = M^64 via 6 squarings; M = [m11 m12; m21 1]
    float pa = m11, pb = m12, pc = m21, pd = 1.0f;
#pragma unroll
    for (int i = 0; i < 6; i++) {
        float na = fmaf(pa, pa, pb * pc);
        float nb = fmaf(pa, pb, pb * pd);
        float nc = fmaf(pc, pa, pd * pc);
        float nd = fmaf(pc, pb, pd * pd);
        pa = na; pb = nb; pc = nc; pd = nd;
    }

    const float4* cf = reinterpret_cast<const float4*>(g_cf) + (size_t)(b * 256 + p) * 64;
    float4 v0 = cf[2 * lane];
    float4 v1 = cf[2 * lane + 1];

    float w1r = fmaf(pa, v0.x, fmaf(pb, v0.z, v1.x));
    float w1i = fmaf(pa, v0.y, fmaf(pb, v0.w, v1.y));
    float w2r = fmaf(pc, v0.x, fmaf(pd, v0.z, v1.z));
    float w2i = fmaf(pc, v0.y, fmaf(pd, v0.w, v1.w));
    float ma = fmaf(pa, pa, pb * pc), mb = fmaf(pa, pb, pb * pd);
    float mc = fmaf(pc, pa, pd * pc), md = fmaf(pc, pb, pd * pd);

#pragma unroll
    for (int d = 1; d < 32; d <<= 1) {
        float oa = __shfl_up_sync(FULL, ma, d);
        float ob = __shfl_up_sync(FULL, mb, d);
        float oc = __shfl_up_sync(FULL, mc, d);
        float od = __shfl_up_sync(FULL, md, d);
        float o1r = __shfl_up_sync(FULL, w1r, d);
        float o1i = __shfl_up_sync(FULL, w1i, d);
        float o2r = __shfl_up_sync(FULL, w2r, d);
        float o2i = __shfl_up_sync(FULL, w2i, d);
        if (lane >= d) {
            w1r = fmaf(ma, o1r, fmaf(mb, o2r, w1r));
            w1i = fmaf(ma, o1i, fmaf(mb, o2i, w1i));
            w2r = fmaf(mc, o1r, fmaf(md, o2r, w2r));
            w2i = fmaf(mc, o1i, fmaf(md, o2i, w2i));
            float na = fmaf(ma, oa, mb * oc), nb = fmaf(ma, ob, mb * od);
            float nc = fmaf(mc, oa, md * oc), nd = fmaf(mc, ob, md * od);
            ma = na; mb = nb; mc = nc; md = nd;
        }
    }

    float e1r = __shfl_up_sync(FULL, w1r, 1);
    float e1i = __shfl_up_sync(FULL, w1i, 1);
    float e2r = __shfl_up_sync(FULL, w2r, 1);
    float e2i = __shfl_up_sync(FULL, w2i, 1);
    if (lane == 0) { e1r = e1i = e2r = e2i = 0.0f; }

    float4* gi = reinterpret_cast<float4*>(g_init) + (size_t)(b * 256 + p) * 64;
    gi[2 * lane] = make_float4(e1r, e1i, e2r, e2i);
    gi[2 * lane + 1] = make_float4(
        fmaf(pa, e1r, fmaf(pb, e2r, v0.x)),
        fmaf(pa, e1i, fmaf(pb, e2i, v0.y)),
        fmaf(pc, e1r, fmaf(pd, e2r, v0.z)),
        fmaf(pc, e1i, fmaf(pd, e2i, v0.w)));
}

// ---------------------------------------------------------------------------
// Fused phase 3: block = one chunk (b,ch) = 64 rows.
// 1) cp.async f tile (64x512) into padded smem
// 2) in-smem column scans (512 independent 2-state recurrences, 64 steps)
// 3) tf32 GEMM  out[64x256] = ys_smem[64x512] @ Cop[512x256] + D*u
// smem: Ys[64][520] + Bs[2][32][264]  = 200704 B
// ---------------------------------------------------------------------------
constexpr int YLD = 520;   // 512 + 8 pad (8 mod 32 -> conflict-free frag reads)
constexpr int BLD = 264;   // 256 + 8 pad

__global__ void __launch_bounds__(256)
fused_scan_gemm2(const float* __restrict__ Cop, float* __restrict__ Out,
                 const float* __restrict__ U, const float* __restrict__ Dv) {
    extern __shared__ float sm[];
    float* Ys = sm;               // [64][YLD]
    float* Bsm = sm + 64 * YLD;   // [2][32][BLD]

    const int b = blockIdx.x >> 6;
    const int ch = blockIdx.x & 63;
    const int row0 = b * Lc + ch * CLEN;
    const int tid = threadIdx.x;
    const int lane = tid & 31, warp = tid >> 5;
    const int g = lane >> 2, t = lane & 3;
    const int wr = (warp & 1) * 32, wc = (warp >> 1) * 64;

    // --- issue f tile loads (group 0) ---
    const float* fbase = g_f + (size_t)row0 * 512;
#pragma unroll
    for (int i = 0; i < 32; i++) {
        int idx = i * 256 + tid;          // 0..8191 float4s
        int r = idx >> 7, c4 = idx & 127;
        cp_async16(Ys + r * YLD + c4 * 4, fbase + r * 512 + c4 * 4);
    }
    asm volatile("cp.async.commit_group;\n" ::);

    auto ldB = [&](int s, int kt) {
#pragma unroll
        for (int i = 0; i < 8; i++) {
            int idx = i * 256 + tid;      // 0..2047 float4s
            int k = idx >> 6, c4 = idx & 63;
            cp_async16(Bsm + s * (32 * BLD) + k * BLD + c4 * 4,
                       Cop + (size_t)(kt * 32 + k) * 256 + c4 * 4);
        }
        asm volatile("cp.async.commit_group;\n" ::);
    };
    ldB(0, 0);                             // group 1 (overlaps the scan)

    asm volatile("cp.async.wait_group 1;\n" ::);   // f tile complete
    __syncthreads();

    // --- in-smem scan: thread owns columns tid and tid+256 ---
    {
        int pA = tid >> 1, cA = tid & 1;
        int nB = tid + 256;
        int pB = nB >> 1, cB = nB & 1;
        float m11a = g_m11[pA], m12a = g_m12[pA], m21a = g_dts[pA];
        float m11b = g_m11[pB], m12b = g_m12[pB], m21b = g_dts[pB];
        float4 ivA = reinterpret_cast<const float4*>(g_init)[(b * 256 + pA) * 64 + ch];
        float4 ivB = reinterpret_cast<const float4*>(g_init)[(b * 256 + pB) * 64 + ch];
        float x1a = cA ? ivA.y : ivA.x, x2a = cA ? ivA.w : ivA.z;
        float x1b = cB ? ivB.y : ivB.x, x2b = cB ? ivB.w : ivB.z;
        float* ca = Ys + tid;
        float* cb = Ys + nB;
#pragma unroll 8
        for (int l = 0; l < CLEN; l++) {
            float fa = ca[l * YLD], fb = cb[l * YLD];
            float n1a = fmaf(m11a, x1a, fmaf(m12a, x2a, fa));
            float n2a = fmaf(m21a, x1a, x2a);
            float n1b = fmaf(m11b, x1b, fmaf(m12b, x2b, fb));
            float n2b = fmaf(m21b, x1b, x2b);
            x1a = n1a; x2a = n2a; x1b = n1b; x2b = n2b;
            ca[l * YLD] = x2a;
            cb[l * YLD] = x2b;
        }
    }
    asm volatile("cp.async.wait_group 0;\n" ::);   // B stage 0 complete
    __syncthreads();                               // scan + B0 visible to all

    // --- GEMM: 64x256x512, warp tile 32x64 (2 m16 x 8 n8), 16 kt steps ---
    float acc[2][8][4];
#pragma unroll
    for (int i = 0; i < 2; i++)
#pragma unroll
        for (int j = 0; j < 8; j++)
#pragma unroll
            for (int q = 0; q < 4; q++) acc[i][j][q] = 0.0f;

    for (int kt = 0; kt < 16; kt++) {
        int s = kt & 1;
        bool more = (kt + 1 < 16);
        if (more) ldB(s ^ 1, kt + 1);

        const float* Bsb = Bsm + s * (32 * BLD);
#pragma unroll
        for (int kk = 0; kk < 4; kk++) {
            uint32_t af[2][4];
#pragma unroll
            for (int mt = 0; mt < 2; mt++) {
                int row = wr + mt * 16 + g;
                int col = kt * 32 + kk * 8 + t;
                af[mt][0] = __float_as_uint(tf32_rna(Ys[row * YLD + col]));
                af[mt][1] = __float_as_uint(tf32_rna(Ys[(row + 8) * YLD + col]));
                af[mt][2] = __float_as_uint(tf32_rna(Ys[row * YLD + col + 4]));
                af[mt][3] = __float_as_uint(tf32_rna(Ys[(row + 8) * YLD + col + 4]));
            }
            uint32_t bf[8][2];
#pragma unroll
            for (int nt = 0; nt < 8; nt++) {
                int col = wc + nt * 8 + g;
                bf[nt][0] = __float_as_uint(Bsb[(kk * 8 + t) * BLD + col]);
                bf[nt][1] = __float_as_uint(Bsb[(kk * 8 + t + 4) * BLD + col]);
            }
#pragma unroll
            for (int mt = 0; mt < 2; mt++)
#pragma unroll
                for (int nt = 0; nt < 8; nt++)
                    mma_tf32_v(acc[mt][nt], af[mt], bf[nt]);
        }
        if (more) asm volatile("cp.async.wait_group 0;\n" ::);
        __syncthreads();
    }

    // --- epilogue: + D*u, write out ---
#pragma unroll
    for (int mt = 0; mt < 2; mt++) {
#pragma unroll
        for (int nt = 0; nt < 8; nt++) {
            int r0 = row0 + wr + mt * 16 + g;
            int cc = wc + nt * 8 + 2 * t;
            float d0 = Dv[cc], d1 = Dv[cc + 1];
            float v0 = fmaf(d0, U[(size_t)r0 * 256 + cc],     acc[mt][nt][0]);
            float v1 = fmaf(d1, U[(size_t)r0 * 256 + cc + 1], acc[mt][nt][1]);
            float v2 = fmaf(d0, U[(size_t)(r0 + 8) * 256 + cc],     acc[mt][nt][2]);
            float v3 = fmaf(d1, U[(size_t)(r0 + 8) * 256 + cc + 1], acc[mt][nt][3]);
            *reinterpret_cast<float2*>(Out + (size_t)r0 * 256 + cc) = make_float2(v0, v1);
            *reinterpret_cast<float2*>(Out + (size_t)(r0 + 8) * 256 + cc) = make_float2(v2, v3);
        }
    }
}

// ---------------------------------------------------------------------------
extern "C" void kernel_launch(void* const* d_in, const int* in_sizes, int n_in,
                              void* d_out, int out_size) {
    const float* u  = (const float*)d_in[0];
    const float* Ad = (const float*)d_in[1];
    const float* Gd = (const float*)d_in[2];
    const float* dt = (const float*)d_in[3];
    const float* Bm = (const float*)d_in[4];
    const float* Cm = (const float*)d_in[5];
    const float* Dv = (const float*)d_in[6];
    float* out = (float*)d_out;

    float *fptr, *bop, *cop;
    cudaGetSymbolAddress((void**)&fptr, g_f);
    cudaGetSymbolAddress((void**)&bop,  g_Bop);
    cudaGetSymbolAddress((void**)&cop,  g_Cop);

    const int smem1 = (2 * 128 * 36 + 2 * 32 * 136) * 4;      // 71680
    const int smem2 = (64 * YLD + 2 * 32 * BLD) * 4;          // 200704
    cudaFuncSetAttribute(gemm_tf32<512, 256>,
                         cudaFuncAttributeMaxDynamicSharedMemorySize, smem1);
    cudaFuncSetAttribute(fused_scan_gemm2,
                         cudaFuncAttributeMaxDynamicSharedMemorySize, smem2);

    prep_kernel<<<256, 512>>>(Ad, Gd, dt, Bm, Cm);

    // GEMM1: f[bl][n(512)] = u[bl][h] @ Bop[h][n]
    gemm_tf32<512, 256><<<dim3(4, 256), 256, smem1>>>(u, bop, fptr);

    scan_local  <<<Bc * NCHUNK, 256>>>();
    scan_combine<<<256, 256>>>();

    // Fused: scan_final + GEMM2 (+ D*u epilogue) straight to out
    fused_scan_gemm2<<<Bc * NCHUNK, 256, smem2>>>(cop, out, u, Dv);
}

// round 7
// speedup vs baseline: 1.1652x; 1.0825x over previous
#include <cuda_runtime.h>
#include <cstdint>

// Problem constants
constexpr int Bc = 8, Lc = 4096;
constexpr int Mrows = Bc * Lc;          // 32768
constexpr int NCHUNK = 64, CLEN = 64;   // 64 chunks of 64 steps

// Scratch (static device arrays -- no allocation allowed)
__device__ float g_f [(size_t)Mrows * 512];   // f = dt_s*Bu : [bl][2p+c] (re/im interleaved)
__device__ float g_Bop[256 * 512];            // [h][n], n = 2p+c, dt_s folded
__device__ float g_Cop[512 * 256];            // [kk][h], kk = 2p+c: +Cre / -Cim
__device__ float g_m11[256], g_m12[256], g_dts[256];
__device__ float g_cf  [Bc * 256 * NCHUNK * 4]; // [b][p][ch] float4 (x1r,x1i,x2r,x2i)
__device__ float g_init[Bc * 256 * NCHUNK * 4]; // same layout

__device__ __forceinline__ float tf32_rna(float x) {
    uint32_t u;
    asm("cvt.rna.tf32.f32 %0, %1;" : "=r"(u) : "f"(x));
    return __uint_as_float(u);
}

__device__ __forceinline__ void cp_async16(void* smem, const void* gmem) {
    uint32_t s = (uint32_t)__cvta_generic_to_shared(smem);
    asm volatile("cp.async.ca.shared.global [%0], [%1], 16;\n" :: "r"(s), "l"(gmem));
}

__device__ __forceinline__ void mma_tf32_v(float c[4], const uint32_t a[4], const uint32_t b[2]) {
    asm volatile(
        "mma.sync.aligned.m16n8k8.row.col.f32.tf32.tf32.f32 "
        "{%0,%1,%2,%3}, {%4,%5,%6,%7}, {%8,%9}, {%0,%1,%2,%3};\n"
        : "+f"(c[0]), "+f"(c[1]), "+f"(c[2]), "+f"(c[3])
        : "r"(a[0]), "r"(a[1]), "r"(a[2]), "r"(a[3]), "r"(b[0]), "r"(b[1]));
}

// ---------------------------------------------------------------------------
// Prep (round-2): per-p recurrence params + operand matrices (tf32 RNA)
// Interleaved layout n = 2p + c  (c=0 re, c=1 im)
// ---------------------------------------------------------------------------
__global__ void prep_kernel(const float* __restrict__ Ad, const float* __restrict__ Gd,
                            const float* __restrict__ dt, const float* __restrict__ Bm,
                            const float* __restrict__ Cm) {
    int h = blockIdx.x;          // 0..255
    int n = threadIdx.x;         // 0..511
    int p = n >> 1;
    int c = n & 1;
    float dts = 1.0f / (1.0f + expf(-dt[p]));
    float G = fmaxf(Gd[p], dts * Ad[p]);
    float A = fmaxf(Ad[p], 0.25f * G * G);

    g_Bop[h * 512 + n] = tf32_rna(dts * Bm[p * 512 + h * 2 + c]);
    float cv = Cm[h * 512 + p * 2 + c];
    g_Cop[n * 256 + h] = tf32_rna(c ? -cv : cv);

    if (h == 0 && c == 0) {
        g_m11[p] = 1.0f - dts * G;
        g_m12[p] = -dts * A;
        g_dts[p] = dts;          // m21; m22 == 1
    }
}

// ---------------------------------------------------------------------------
// GEMM1 (+ fused local scan): f = u @ Bop  (M=32768, N=512, K=256)
// Round-2 mainloop verbatim. Epilogue: write f, then stage tile in smem and
// run the per-chunk local scans (zero init) -> g_cf.
// ---------------------------------------------------------------------------
__global__ void __launch_bounds__(256, 2)
gemm1_scan(const float* __restrict__ A, const float* __restrict__ Bm,
           float* __restrict__ C) {
    constexpr int N = 512, K = 256, nk = K / 32;
    extern __shared__ float sm[];
    float* As = sm;                // 2 stages * 128*36
    float* Bs = sm + 2 * 128 * 36; // 2 stages * 32*136

    const int tid  = threadIdx.x;
    const int lane = tid & 31, warp = tid >> 5;
    const int g = lane >> 2, t = lane & 3;
    const int wr = (warp & 1) * 64, wc = (warp >> 1) * 32;
    const int m0 = blockIdx.y * 128, n0 = blockIdx.x * 128;

    float acc[4][4][4];
#pragma unroll
    for (int i = 0; i < 4; i++)
#pragma unroll
        for (int j = 0; j < 4; j++)
#pragma unroll
            for (int q = 0; q < 4; q++) acc[i][j][q] = 0.0f;

    float4 aReg[4];

    auto ldgA = [&](int kt) {
#pragma unroll
        for (int i = 0; i < 4; i++) {
            int idx = i * 256 + tid;
            int m = idx >> 3, c4 = idx & 7;
            aReg[i] = *reinterpret_cast<const float4*>(
                A + (size_t)(m0 + m) * K + kt * 32 + c4 * 4);
        }
    };
    auto stsA = [&](int s) {
#pragma unroll
        for (int i = 0; i < 4; i++) {
            int idx = i * 256 + tid;
            int m = idx >> 3, c4 = idx & 7;
            float4 v = aReg[i];
            v.x = tf32_rna(v.x); v.y = tf32_rna(v.y);
            v.z = tf32_rna(v.z); v.w = tf32_rna(v.w);
            *reinterpret_cast<float4*>(As + s * 4608 + m * 36 + c4 * 4) = v;
        }
    };
    auto ldB = [&](int s, int kt) {
#pragma unroll
        for (int i = 0; i < 4; i++) {
            int idx = i * 256 + tid;
            int k = idx >> 5, c = idx & 31;
            cp_async16(Bs + s * 4352 + k * 136 + c * 4,
                       Bm + (size_t)(kt * 32 + k) * N + n0 + c * 4);
        }
        asm volatile("cp.async.commit_group;\n" ::);
    };

    ldB(0, 0);
    ldgA(0); stsA(0);
    asm volatile("cp.async.wait_group 0;\n" ::);
    __syncthreads();

    for (int kt = 0; kt < nk; kt++) {
        int s = kt & 1;
        bool more = (kt + 1 < nk);
        if (more) { ldB(s ^ 1, kt + 1); ldgA(kt + 1); }

        const float* Asb = As + s * 4608;
        const float* Bsb = Bs + s * 4352;
#pragma unroll
        for (int kk = 0; kk < 4; kk++) {
            uint32_t af[4][4];
#pragma unroll
            for (int mt = 0; mt < 4; mt++) {
                int row = wr + mt * 16 + g;
                int col = kk * 8 + t;
                af[mt][0] = __float_as_uint(Asb[row * 36 + col]);
                af[mt][1] = __float_as_uint(Asb[(row + 8) * 36 + col]);
                af[mt][2] = __float_as_uint(Asb[row * 36 + col + 4]);
                af[mt][3] = __float_as_uint(Asb[(row + 8) * 36 + col + 4]);
            }
            uint32_t bf[4][2];
#pragma unroll
            for (int nt = 0; nt < 4; nt++) {
                int col = wc + nt * 8 + g;
                bf[nt][0] = __float_as_uint(Bsb[(kk * 8 + t) * 136 + col]);
                bf[nt][1] = __float_as_uint(Bsb[(kk * 8 + t + 4) * 136 + col]);
            }
#pragma unroll
            for (int mt = 0; mt < 4; mt++)
#pragma unroll
                for (int nt = 0; nt < 4; nt++)
                    mma_tf32_v(acc[mt][nt], af[mt], bf[nt]);
        }
        if (more) {
            stsA(s ^ 1);
            asm volatile("cp.async.wait_group 0;\n" ::);
        }
        __syncthreads();
    }

    // --- epilogue: write f to gmem AND stage tile into smem for local scan ---
    float* Ys = sm;   // reuse pipeline smem: 128 x 132 floats (<= 17920)
#pragma unroll
    for (int mt = 0; mt < 4; mt++) {
#pragma unroll
        for (int nt = 0; nt < 4; nt++) {
            int rl = wr + mt * 16 + g;
            int cc = wc + nt * 8 + 2 * t;
            int r0 = m0 + rl;
            float2 v01 = make_float2(acc[mt][nt][0], acc[mt][nt][1]);
            float2 v23 = make_float2(acc[mt][nt][2], acc[mt][nt][3]);
            *reinterpret_cast<float2*>(C + (size_t)r0 * N + n0 + cc) = v01;
            *reinterpret_cast<float2*>(C + (size_t)(r0 + 8) * N + n0 + cc) = v23;
            *reinterpret_cast<float2*>(Ys + rl * 132 + cc) = v01;
            *reinterpret_cast<float2*>(Ys + (rl + 8) * 132 + cc) = v23;
        }
    }
    __syncthreads();

    // local scan: thread -> (col 0..127, chunk 0..1), zero init
    {
        int col = tid & 127, chunk = tid >> 7;
        int ng = n0 + col;
        int p = ng >> 1, c = ng & 1;
        float m11 = g_m11[p], m12 = g_m12[p], m21 = g_dts[p];
        float x1 = 0.0f, x2 = 0.0f;
        const float* base = Ys + (chunk * 64) * 132 + col;
#pragma unroll 8
        for (int j = 0; j < CLEN; j++) {
            float fv = base[j * 132];
            float n1 = fmaf(m11, x1, fmaf(m12, x2, fv));
            float n2 = fmaf(m21, x1, x2);
            x1 = n1; x2 = n2;
        }
        int b = m0 >> 12;
        int ch = ((m0 & 4095) >> 6) + chunk;
        float* cfp = g_cf + ((size_t)(b * 256 + p) * 64 + ch) * 4;
        cfp[c]     = x1;   // c=0 -> x1r, c=1 -> x1i
        cfp[2 + c] = x2;   // c=0 -> x2r, c=1 -> x2i
    }
}

// ---------------------------------------------------------------------------
// Scan phase 2 (round-2): warp-parallel cross-chunk combine
// ---------------------------------------------------------------------------
__global__ void __launch_bounds__(256) scan_combine() {
    const unsigned FULL = 0xFFFFFFFFu;
    int wg = blockIdx.x * 8 + (threadIdx.x >> 5);   // 0..2047
    int lane = threadIdx.x & 31;
    int b = wg >> 8, p = wg & 255;

    float m11 = g_m11[p], m12 = g_m12[p], m21 = g_dts[p];
    float pa = m11, pb = m12, pc = m21, pd = 1.0f;
#pragma unroll
    for (int i = 0; i < 6; i++) {
        float na = fmaf(pa, pa, pb * pc);
        float nb = fmaf(pa, pb, pb * pd);
        float nc = fmaf(pc, pa, pd * pc);
        float nd = fmaf(pc, pb, pd * pd);
        pa = na; pb = nb; pc = nc; pd = nd;
    }

    const float4* cf = reinterpret_cast<const float4*>(g_cf) + (size_t)(b * 256 + p) * 64;
    float4 v0 = cf[2 * lane];
    float4 v1 = cf[2 * lane + 1];

    float w1r = fmaf(pa, v0.x, fmaf(pb, v0.z, v1.x));
    float w1i = fmaf(pa, v0.y, fmaf(pb, v0.w, v1.y));
    float w2r = fmaf(pc, v0.x, fmaf(pd, v0.z, v1.z));
    float w2i = fmaf(pc, v0.y, fmaf(pd, v0.w, v1.w));
    float ma = fmaf(pa, pa, pb * pc), mb = fmaf(pa, pb, pb * pd);
    float mc = fmaf(pc, pa, pd * pc), md = fmaf(pc, pb, pd * pd);

#pragma unroll
    for (int d = 1; d < 32; d <<= 1) {
        float oa = __shfl_up_sync(FULL, ma, d);
        float ob = __shfl_up_sync(FULL, mb, d);
        float oc = __shfl_up_sync(FULL, mc, d);
        float od = __shfl_up_sync(FULL, md, d);
        float o1r = __shfl_up_sync(FULL, w1r, d);
        float o1i = __shfl_up_sync(FULL, w1i, d);
        float o2r = __shfl_up_sync(FULL, w2r, d);
        float o2i = __shfl_up_sync(FULL, w2i, d);
        if (lane >= d) {
            w1r = fmaf(ma, o1r, fmaf(mb, o2r, w1r));
            w1i = fmaf(ma, o1i, fmaf(mb, o2i, w1i));
            w2r = fmaf(mc, o1r, fmaf(md, o2r, w2r));
            w2i = fmaf(mc, o1i, fmaf(md, o2i, w2i));
            float na = fmaf(ma, oa, mb * oc), nb = fmaf(ma, ob, mb * od);
            float nc = fmaf(mc, oa, md * oc), nd = fmaf(mc, ob, md * od);
            ma = na; mb = nb; mc = nc; md = nd;
        }
    }

    float e1r = __shfl_up_sync(FULL, w1r, 1);
    float e1i = __shfl_up_sync(FULL, w1i, 1);
    float e2r = __shfl_up_sync(FULL, w2r, 1);
    float e2i = __shfl_up_sync(FULL, w2i, 1);
    if (lane == 0) { e1r = e1i = e2r = e2i = 0.0f; }

    float4* gi = reinterpret_cast<float4*>(g_init) + (size_t)(b * 256 + p) * 64;
    gi[2 * lane] = make_float4(e1r, e1i, e2r, e2i);
    gi[2 * lane + 1] = make_float4(
        fmaf(pa, e1r, fmaf(pb, e2r, v0.x)),
        fmaf(pa, e1i, fmaf(pb, e2i, v0.y)),
        fmaf(pc, e1r, fmaf(pd, e2r, v0.z)),
        fmaf(pc, e1i, fmaf(pd, e2i, v0.w)));
}

// ---------------------------------------------------------------------------
// GEMM2 (+ fused final scan): out = ys @ Cop + D*u, ys computed in-smem
// from f slabs + g_init. M=32768, N=256, K=512. Round-2 mainloop structure;
// per-slab: after stsA (raw f), 64 threads scan the 32 k-columns x 2 chunks
// in place (writing tf32-rounded x2), then MMAs consume ys.
// ---------------------------------------------------------------------------
__global__ void __launch_bounds__(256, 2)
gemm2_scan(const float* __restrict__ A, const float* __restrict__ Bm,
           float* __restrict__ Out, const float* __restrict__ U,
           const float* __restrict__ Dv) {
    constexpr int N = 256, K = 512, nk = K / 32;
    extern __shared__ float sm[];
    float* As = sm;                // 2 stages * 128*36
    float* Bs = sm + 2 * 128 * 36; // 2 stages * 32*136

    const int tid  = threadIdx.x;
    const int lane = tid & 31, warp = tid >> 5;
    const int g = lane >> 2, t = lane & 3;
    const int wr = (warp & 1) * 64, wc = (warp >> 1) * 32;
    const int m0 = blockIdx.y * 128, n0 = blockIdx.x * 128;
    const int b = m0 >> 12;
    const int ch0 = (m0 & 4095) >> 6;

    float acc[4][4][4];
#pragma unroll
    for (int i = 0; i < 4; i++)
#pragma unroll
        for (int j = 0; j < 4; j++)
#pragma unroll
            for (int q = 0; q < 4; q++) acc[i][j][q] = 0.0f;

    float4 aReg[4];

    auto ldgA = [&](int kt) {
#pragma unroll
        for (int i = 0; i < 4; i++) {
            int idx = i * 256 + tid;
            int m = idx >> 3, c4 = idx & 7;
            aReg[i] = *reinterpret_cast<const float4*>(
                A + (size_t)(m0 + m) * K + kt * 32 + c4 * 4);
        }
    };
    auto stsA = [&](int s) {        // raw f (scan rounds afterwards)
#pragma unroll
        for (int i = 0; i < 4; i++) {
            int idx = i * 256 + tid;
            int m = idx >> 3, c4 = idx & 7;
            *reinterpret_cast<float4*>(As + s * 4608 + m * 36 + c4 * 4) = aReg[i];
        }
    };
    auto ldB = [&](int s, int kt) {
#pragma unroll
        for (int i = 0; i < 4; i++) {
            int idx = i * 256 + tid;
            int k = idx >> 5, c = idx & 31;
            cp_async16(Bs + s * 4352 + k * 136 + c * 4,
                       Bm + (size_t)(kt * 32 + k) * N + n0 + c * 4);
        }
        asm volatile("cp.async.commit_group;\n" ::);
    };
    // per-slab scan: f -> ys in place (tf32-rounded)
    auto scan = [&](int s, int kt) {
        if (tid < 64) {
            int col = tid & 31, chunk = tid >> 5;
            int kg = kt * 32 + col;
            int p = kg >> 1, c = kg & 1;
            float m11 = g_m11[p], m12 = g_m12[p], m21 = g_dts[p];
            float4 iv = reinterpret_cast<const float4*>(g_init)
                            [(size_t)(b * 256 + p) * 64 + ch0 + chunk];
            float x1 = c ? iv.y : iv.x;
            float x2 = c ? iv.w : iv.z;
            float* base = As + s * 4608 + (chunk * 64) * 36 + col;
#pragma unroll 8
            for (int j = 0; j < CLEN; j++) {
                float fv = base[j * 36];
                float n1 = fmaf(m11, x1, fmaf(m12, x2, fv));
                float n2 = fmaf(m21, x1, x2);
                x1 = n1; x2 = n2;
                base[j * 36] = tf32_rna(x2);
            }
        }
    };

    // prologue
    ldB(0, 0);
    ldgA(0); stsA(0);
    __syncthreads();            // stsA(0) visible
    scan(0, 0);
    asm volatile("cp.async.wait_group 0;\n" ::);
    __syncthreads();            // scan(0) + B0 visible

    for (int kt = 0; kt < nk; kt++) {
        int s = kt & 1;
        bool more = (kt + 1 < nk);
        if (more) { ldB(s ^ 1, kt + 1); ldgA(kt + 1); }

        const float* Asb = As + s * 4608;
        const float* Bsb = Bs + s * 4352;
#pragma unroll
        for (int kk = 0; kk < 4; kk++) {
            uint32_t af[4][4];
#pragma unroll
            for (int mt = 0; mt < 4; mt++) {
                int row = wr + mt * 16 + g;
                int col = kk * 8 + t;
                af[mt][0] = __float_as_uint(Asb[row * 36 + col]);
                af[mt][1] = __float_as_uint(Asb[(row + 8) * 36 + col]);
                af[mt][2] = __float_as_uint(Asb[row * 36 + col + 4]);
                af[mt][3] = __float_as_uint(Asb[(row + 8) * 36 + col + 4]);
            }
            uint32_t bf[4][2];
#pragma unroll
            for (int nt = 0; nt < 4; nt++) {
                int col = wc + nt * 8 + g;
                bf[nt][0] = __float_as_uint(Bsb[(kk * 8 + t) * 136 + col]);
                bf[nt][1] = __float_as_uint(Bsb[(kk * 8 + t + 4) * 136 + col]);
            }
#pragma unroll
            for (int mt = 0; mt < 4; mt++)
#pragma unroll
                for (int nt = 0; nt < 4; nt++)
                    mma_tf32_v(acc[mt][nt], af[mt], bf[nt]);
        }
        if (more) {
            stsA(s ^ 1);
            asm volatile("cp.async.wait_group 0;\n" ::);
        }
        __syncthreads();        // MMAs(s) done; stsA(s^1) visible
        if (more) {
            scan(s ^ 1, kt + 1);
            __syncthreads();    // ys(s^1) visible for next iteration
        }
    }

    // epilogue: + D*u, write out
#pragma unroll
    for (int mt = 0; mt < 4; mt++) {
#pragma unroll
        for (int nt = 0; nt < 4; nt++) {
            int r0 = m0 + wr + mt * 16 + g;
            int cc = n0 + wc + nt * 8 + 2 * t;
            float d0 = Dv[cc], d1 = Dv[cc + 1];
            float v0 = fmaf(d0, U[(size_t)r0 * 256 + cc],     acc[mt][nt][0]);
            float v1 = fmaf(d1, U[(size_t)r0 * 256 + cc + 1], acc[mt][nt][1]);
            float v2 = fmaf(d0, U[(size_t)(r0 + 8) * 256 + cc],     acc[mt][nt][2]);
            float v3 = fmaf(d1, U[(size_t)(r0 + 8) * 256 + cc + 1], acc[mt][nt][3]);
            *reinterpret_cast<float2*>(Out + (size_t)r0 * N + cc) = make_float2(v0, v1);
            *reinterpret_cast<float2*>(Out + (size_t)(r0 + 8) * N + cc) = make_float2(v2, v3);
        }
    }
}

// ---------------------------------------------------------------------------
extern "C" void kernel_launch(void* const* d_in, const int* in_sizes, int n_in,
                              void* d_out, int out_size) {
    const float* u  = (const float*)d_in[0];
    const float* Ad = (const float*)d_in[1];
    const float* Gd = (const float*)d_in[2];
    const float* dt = (const float*)d_in[3];
    const float* Bm = (const float*)d_in[4];
    const float* Cm = (const float*)d_in[5];
    const float* Dv = (const float*)d_in[6];
    float* out = (float*)d_out;

    float *fptr, *bop, *cop;
    cudaGetSymbolAddress((void**)&fptr, g_f);
    cudaGetSymbolAddress((void**)&bop,  g_Bop);
    cudaGetSymbolAddress((void**)&cop,  g_Cop);

    const int smem_bytes = (2 * 128 * 36 + 2 * 32 * 136) * 4; // 71680
    cudaFuncSetAttribute(gemm1_scan,
                         cudaFuncAttributeMaxDynamicSharedMemorySize, smem_bytes);
    cudaFuncSetAttribute(gemm2_scan,
                         cudaFuncAttributeMaxDynamicSharedMemorySize, smem_bytes);

    prep_kernel<<<256, 512>>>(Ad, Gd, dt, Bm, Cm);

    // GEMM1 + local scan: f = u @ Bop, g_cf from acc tiles
    gemm1_scan<<<dim3(4, 256), 256, smem_bytes>>>(u, bop, fptr);

    scan_combine<<<256, 256>>>();

    // GEMM2 + final scan: out = scan(f) @ Cop + D*u
    gemm2_scan<<<dim3(2, 256), 256, smem_bytes>>>(fptr, cop, out, u, Dv);
}